// round 6
// baseline (speedup 1.0000x reference)
#include <cuda_runtime.h>
#include <math.h>

// ---------------- problem constants ----------------
#define N_STMT 100000
#define N_FUNC 50000
#define T_TOK  16
#define VOCAB  50000
#define C_DIM  128
#define H_HEAD 8
#define D_HEAD 16
#define L_LAYER 2
#define E_EDGE 200000

// ---------------- scratch arena (floats) ----------------
#define SZ_S ((size_t)N_STMT * C_DIM)   // 12.8M
#define SZ_F ((size_t)N_FUNC * C_DIM)   // 6.4M
#define OFF_X0   ((size_t)0)
#define OFF_X1   (OFF_X0 + SZ_S)
#define OFF_XN0  (OFF_X1 + SZ_F)
#define OFF_XN1  (OFF_XN0 + SZ_S)
#define OFF_K0   (OFF_XN1 + SZ_F)
#define OFF_Q0   (OFF_K0 + SZ_S)
#define OFF_V0   (OFF_Q0 + SZ_S)
#define OFF_K1   (OFF_V0 + SZ_S)
#define OFF_Q1   (OFF_K1 + SZ_F)
#define OFF_V1   (OFF_Q1 + SZ_F)
#define OFF_KR   (OFF_V1 + SZ_F)
#define OFF_VR   (OFF_KR + SZ_S)
#define OFF_AGG0 (OFF_VR + SZ_S)
#define OFF_AGG1 (OFF_AGG0 + SZ_S)
#define OFF_LOG  (OFF_AGG1 + SZ_F)
#define OFF_M    (OFF_LOG + (size_t)E_EDGE * H_HEAD)
#define OFF_SS   (OFF_M + (size_t)N_STMT * H_HEAD)
#define SCRATCH_TOTAL (OFF_SS + (size_t)N_STMT * H_HEAD)

__device__ float g_scratch[SCRATCH_TOTAL];

// ---------------- device helpers ----------------
__device__ __forceinline__ float gelu_tanh(float x) {
    const float c = 0.7978845608028654f;  // sqrt(2/pi)
    float x3 = x * x * x;
    return 0.5f * x * (1.0f + tanhf(c * (x + 0.044715f * x3)));
}

__device__ __forceinline__ void atomicMaxF(float* addr, float v) {
    if (v >= 0.0f) atomicMax((int*)addr, __float_as_int(v));
    else           atomicMin((unsigned int*)addr, __float_as_uint(v));
}

// ---------------- fills ----------------
__global__ void fill_kernel(float* __restrict__ p, float v, int n) {
    int i = blockIdx.x * blockDim.x + threadIdx.x;
    if (i < n) p[i] = v;
}

// init m = -inf and s = 0 in one pass
__global__ void init_ms_kernel(float* __restrict__ m, float* __restrict__ s, int n) {
    int i = blockIdx.x * blockDim.x + threadIdx.x;
    if (i < n) { m[i] = -INFINITY; s[i] = 0.0f; }
}

// s <- 1/(s + 1e-16)  (per node,head reciprocal, off the edge hot path)
__global__ void inv_kernel(float* __restrict__ s, int n) {
    int i = blockIdx.x * blockDim.x + threadIdx.x;
    if (i < n) s[i] = 1.0f / (s[i] + 1e-16f);
}

// ---------------- embedding mean-pool + relu ----------------
__global__ void pool_kernel(const int* __restrict__ tok, const float* __restrict__ emb,
                            float* __restrict__ out, int N) {
    int n = blockIdx.x;
    int c = threadIdx.x;
    __shared__ int ts[T_TOK];
    if (c < T_TOK) ts[c] = tok[n * T_TOK + c];
    __syncthreads();
    float s = 0.0f;
#pragma unroll
    for (int t = 0; t < T_TOK; t++)
        s += emb[(size_t)ts[t] * C_DIM + c];
    s *= (1.0f / (float)T_TOK);
    out[(size_t)n * C_DIM + c] = fmaxf(s, 0.0f);
}

// ---------------- GEMM: Y[N,128] = epi( act_in(X)[N,128] @ W[128,128] + b ) ----------------
// EPI: 0 = none, 1 = relu, 2 = skip-blend (g*o + (1-g)*Xold, g = sigmoid(*skipp))
#define GBM 64
#define GBK 32
template<int IN_GELU, int EPI>
__global__ void gemm128(const float* __restrict__ X, const float* __restrict__ W,
                        const float* __restrict__ bias, float* __restrict__ Y,
                        const float* __restrict__ Xold, const float* __restrict__ skipp,
                        int N) {
    __shared__ float Xs[GBM][GBK];
    __shared__ float Ws[GBK][C_DIM];
    int tid = threadIdx.x;          // 256 threads
    int tx = tid & 15;              // col group: cols tx*8 .. tx*8+7
    int ty = tid >> 4;              // row group: rows ty*4 .. ty*4+3
    int row0 = blockIdx.x * GBM;

    float acc[4][8];
#pragma unroll
    for (int i = 0; i < 4; i++)
#pragma unroll
        for (int j = 0; j < 8; j++) acc[i][j] = 0.0f;

    for (int kc = 0; kc < C_DIM; kc += GBK) {
        // X tile: 64x32 floats = 512 float4, 2 per thread
#pragma unroll
        for (int v = 0; v < 2; v++) {
            int idx = tid + v * 256;
            int r = idx >> 3;
            int kk = (idx & 7) << 2;
            int grow = row0 + r;
            float4 val;
            if (grow < N) val = *(const float4*)&X[(size_t)grow * C_DIM + kc + kk];
            else          val = make_float4(0.f, 0.f, 0.f, 0.f);
            if (IN_GELU) {
                val.x = gelu_tanh(val.x); val.y = gelu_tanh(val.y);
                val.z = gelu_tanh(val.z); val.w = gelu_tanh(val.w);
            }
            *(float4*)&Xs[r][kk] = val;
        }
        // W tile: 32x128 floats = 1024 float4, 4 per thread
#pragma unroll
        for (int v = 0; v < 4; v++) {
            int idx = tid + v * 256;
            int r = idx >> 5;
            int cc = (idx & 31) << 2;
            *(float4*)&Ws[r][cc] = *(const float4*)&W[(size_t)(kc + r) * C_DIM + cc];
        }
        __syncthreads();
#pragma unroll
        for (int k = 0; k < GBK; k++) {
            float a[4];
#pragma unroll
            for (int i = 0; i < 4; i++) a[i] = Xs[ty * 4 + i][k];
            float4 b0 = *(float4*)&Ws[k][tx * 8];
            float4 b1 = *(float4*)&Ws[k][tx * 8 + 4];
            float bb[8] = {b0.x, b0.y, b0.z, b0.w, b1.x, b1.y, b1.z, b1.w};
#pragma unroll
            for (int i = 0; i < 4; i++)
#pragma unroll
                for (int j = 0; j < 8; j++)
                    acc[i][j] = fmaf(a[i], bb[j], acc[i][j]);
        }
        __syncthreads();
    }

    float g = 0.0f, og = 0.0f;
    if (EPI == 2) {
        g = 1.0f / (1.0f + expf(-skipp[0]));
        og = 1.0f - g;
    }
#pragma unroll
    for (int i = 0; i < 4; i++) {
        int grow = row0 + ty * 4 + i;
        if (grow < N) {
#pragma unroll
            for (int j = 0; j < 8; j++) {
                int col = tx * 8 + j;
                float vv = acc[i][j] + bias[col];
                if (EPI == 1) vv = fmaxf(vv, 0.0f);
                if (EPI == 2) vv = g * vv + og * Xold[(size_t)grow * C_DIM + col];
                Y[(size_t)grow * C_DIM + col] = vv;
            }
        }
    }
}

// ---------------- per-head relation transform: Y[n,h,e] = sum_d X[n,h,d] * A[h,d,e] ----------------
__global__ void rel_kernel(const float* __restrict__ X, const float* __restrict__ A,
                           float* __restrict__ Y, int N) {
    __shared__ float As[H_HEAD * D_HEAD * D_HEAD];  // 2048
    __shared__ float xin[4][C_DIM];
    int tid = threadIdx.y * C_DIM + threadIdx.x;
    for (int i = tid; i < H_HEAD * D_HEAD * D_HEAD; i += 512) As[i] = A[i];
    int n = blockIdx.x * 4 + threadIdx.y;
    int c = threadIdx.x;
    int h = c >> 4, e = c & 15;
    if (n < N) xin[threadIdx.y][c] = X[(size_t)n * C_DIM + c];
    __syncthreads();
    if (n < N) {
        float s = 0.0f;
#pragma unroll
        for (int d = 0; d < D_HEAD; d++)
            s = fmaf(xin[threadIdx.y][h * 16 + d], As[(h * 16 + d) * 16 + e], s);
        Y[(size_t)n * C_DIM + c] = s;
    }
}

// ---------------- edge kernels ----------------
__global__ void edge_logits_kernel(const int* __restrict__ src, const int* __restrict__ dst,
                                   const float* __restrict__ Q, const float* __restrict__ KR,
                                   const float* __restrict__ prel,
                                   float* __restrict__ logits, float* __restrict__ m) {
    int idx = blockIdx.x * blockDim.x + threadIdx.x;
    if (idx >= E_EDGE * H_HEAD) return;
    int e = idx >> 3;
    int h = idx & 7;
    int s = src[e], d = dst[e];
    const float4* qp = (const float4*)&Q[(size_t)d * C_DIM + h * 16];
    const float4* kp = (const float4*)&KR[(size_t)s * C_DIM + h * 16];
    float acc = 0.0f;
#pragma unroll
    for (int i = 0; i < 4; i++) {
        float4 qa = qp[i], ka = kp[i];
        acc += qa.x * ka.x + qa.y * ka.y + qa.z * ka.z + qa.w * ka.w;
    }
    float lg = acc * prel[h] * 0.25f;   // scale = 1/sqrt(16)
    logits[idx] = lg;
    atomicMaxF(&m[d * H_HEAD + h], lg);
}

__global__ void edge_exp_kernel(const int* __restrict__ dst,
                                float* __restrict__ logits,
                                const float* __restrict__ m, float* __restrict__ ssum) {
    int idx = blockIdx.x * blockDim.x + threadIdx.x;
    if (idx >= E_EDGE * H_HEAD) return;
    int e = idx >> 3;
    int h = idx & 7;
    int d = dst[e];
    float v = expf(logits[idx] - m[d * H_HEAD + h]);
    logits[idx] = v;
    atomicAdd(&ssum[d * H_HEAD + h], v);
}

// sinv holds precomputed 1/(s+1e-16)
__global__ void edge_scatter_kernel(const int* __restrict__ src, const int* __restrict__ dst,
                                    const float* __restrict__ VR, const float* __restrict__ logits,
                                    const float* __restrict__ sinv, float* __restrict__ agg) {
    int idx = blockIdx.x * blockDim.x + threadIdx.x;
    if (idx >= E_EDGE * H_HEAD) return;
    int e = idx >> 3;
    int h = idx & 7;
    int sn = src[e], d = dst[e];
    float alpha = logits[idx] * sinv[d * H_HEAD + h];
    const float4* vp = (const float4*)&VR[(size_t)sn * C_DIM + h * 16];
    float* ap = &agg[(size_t)d * C_DIM + h * 16];
#pragma unroll
    for (int i = 0; i < 4; i++) {
        float4 vv = vp[i];
        atomicAdd(ap + 4 * i + 0, vv.x * alpha);
        atomicAdd(ap + 4 * i + 1, vv.y * alpha);
        atomicAdd(ap + 4 * i + 2, vv.z * alpha);
        atomicAdd(ap + 4 * i + 3, vv.w * alpha);
    }
}

// ---------------- host orchestration ----------------
static inline int cdiv(int a, int b) { return (a + b - 1) / b; }

extern "C" void kernel_launch(void* const* d_in, const int* in_sizes, int n_in,
                              void* d_out, int out_size) {
    (void)in_sizes; (void)n_in; (void)out_size;
    const int*   tok_s = (const int*)d_in[0];
    const int*   tok_f = (const int*)d_in[1];
    const int*   esrc[3] = {(const int*)d_in[2], (const int*)d_in[4], (const int*)d_in[6]};
    const int*   edst[3] = {(const int*)d_in[3], (const int*)d_in[5], (const int*)d_in[7]};
    const float* emb   = (const float*)d_in[8];
    const float* lin_w = (const float*)d_in[9];
    const float* lin_b = (const float*)d_in[10];
    const float* kw = (const float*)d_in[11], *kbi = (const float*)d_in[12];
    const float* qw = (const float*)d_in[13], *qbi = (const float*)d_in[14];
    const float* vw = (const float*)d_in[15], *vbi = (const float*)d_in[16];
    const float* aw = (const float*)d_in[17], *abi = (const float*)d_in[18];
    const float* skip  = (const float*)d_in[19];
    const float* a_rel = (const float*)d_in[20];
    const float* m_rel = (const float*)d_in[21];
    const float* p_rel = (const float*)d_in[22];
    float* out = (float*)d_out;

    float* S = nullptr;
    cudaGetSymbolAddress((void**)&S, g_scratch);

    float* x[2]    = {S + OFF_X0,  S + OFF_X1};
    float* xn[2]   = {S + OFF_XN0, S + OFF_XN1};
    float* bufK[2] = {S + OFF_K0,  S + OFF_K1};
    float* bufQ[2] = {S + OFF_Q0,  S + OFF_Q1};
    float* bufV[2] = {S + OFF_V0,  S + OFF_V1};
    float* kr   = S + OFF_KR;
    float* vr   = S + OFF_VR;
    float* agg[2] = {S + OFF_AGG0, S + OFF_AGG1};
    float* lg   = S + OFF_LOG;
    float* mbuf = S + OFF_M;
    float* sbuf = S + OFF_SS;

    const int NN[2] = {N_STMT, N_FUNC};
    const int ST[3] = {0, 0, 1};
    const int DT[3] = {0, 1, 0};
    const int nEH = E_EDGE * H_HEAD;

    // ---- encode: pool(+relu) into agg buffers, then per-type linear + relu ----
    pool_kernel<<<N_STMT, C_DIM>>>(tok_s, emb, agg[0], N_STMT);
    pool_kernel<<<N_FUNC, C_DIM>>>(tok_f, emb, agg[1], N_FUNC);
    gemm128<0, 1><<<cdiv(N_STMT, GBM), 256>>>(agg[0], lin_w, lin_b, x[0], nullptr, nullptr, N_STMT);
    gemm128<0, 1><<<cdiv(N_FUNC, GBM), 256>>>(agg[1], lin_w + C_DIM * C_DIM, lin_b + C_DIM,
                                              x[1], nullptr, nullptr, N_FUNC);

    float* cur[2] = {x[0], x[1]};
    float* nxt[2] = {xn[0], xn[1]};

    for (int l = 0; l < L_LAYER; l++) {
        // projections
        for (int t = 0; t < 2; t++) {
            size_t wo = (size_t)(l * 2 + t) * C_DIM * C_DIM;
            size_t bo = (size_t)(l * 2 + t) * C_DIM;
            int nb = cdiv(NN[t], GBM);
            gemm128<0, 0><<<nb, 256>>>(cur[t], kw + wo, kbi + bo, bufK[t], nullptr, nullptr, NN[t]);
            gemm128<0, 0><<<nb, 256>>>(cur[t], qw + wo, qbi + bo, bufQ[t], nullptr, nullptr, NN[t]);
            gemm128<0, 0><<<nb, 256>>>(cur[t], vw + wo, vbi + bo, bufV[t], nullptr, nullptr, NN[t]);
        }
        // zero aggregators
        fill_kernel<<<cdiv(N_STMT * C_DIM, 256), 256>>>(agg[0], 0.0f, N_STMT * C_DIM);
        fill_kernel<<<cdiv(N_FUNC * C_DIM, 256), 256>>>(agg[1], 0.0f, N_FUNC * C_DIM);

        for (int r = 0; r < 3; r++) {
            int st = ST[r], dt = DT[r];
            size_t ro = (size_t)(l * 3 + r) * H_HEAD * D_HEAD * D_HEAD;
            dim3 rb(C_DIM, 4);
            rel_kernel<<<cdiv(NN[st], 4), rb>>>(bufK[st], a_rel + ro, kr, NN[st]);
            rel_kernel<<<cdiv(NN[st], 4), rb>>>(bufV[st], m_rel + ro, vr, NN[st]);

            int ndh = NN[dt] * H_HEAD;
            init_ms_kernel<<<cdiv(ndh, 256), 256>>>(mbuf, sbuf, ndh);

            const float* pr = p_rel + (size_t)(l * 3 + r) * H_HEAD;
            edge_logits_kernel<<<cdiv(nEH, 256), 256>>>(esrc[r], edst[r], bufQ[dt], kr, pr, lg, mbuf);
            edge_exp_kernel<<<cdiv(nEH, 256), 256>>>(edst[r], lg, mbuf, sbuf);
            inv_kernel<<<cdiv(ndh, 256), 256>>>(sbuf, ndh);
            edge_scatter_kernel<<<cdiv(nEH, 256), 256>>>(esrc[r], edst[r], vr, lg, sbuf, agg[dt]);
        }

        // output projection with gelu-in + skip blend
        for (int t = 0; t < 2; t++) {
            size_t wo = (size_t)(l * 2 + t) * C_DIM * C_DIM;
            size_t bo = (size_t)(l * 2 + t) * C_DIM;
            float* yo = (l == L_LAYER - 1)
                        ? out + (t == 1 ? (size_t)N_STMT * C_DIM : 0)
                        : nxt[t];
            gemm128<1, 2><<<cdiv(NN[t], GBM), 256>>>(agg[t], aw + wo, abi + bo, yo,
                                                     cur[t], skip + (l * 2 + t), NN[t]);
        }
        // swap
        float* t0 = cur[0]; float* t1 = cur[1];
        cur[0] = nxt[0]; cur[1] = nxt[1];
        nxt[0] = t0; nxt[1] = t1;
    }
}

// round 8
// speedup vs baseline: 1.2028x; 1.2028x over previous
#include <cuda_runtime.h>
#include <math.h>

// ---------------- problem constants ----------------
#define N_STMT 100000
#define N_FUNC 50000
#define T_TOK  16
#define VOCAB  50000
#define C_DIM  128
#define H_HEAD 8
#define D_HEAD 16
#define L_LAYER 2
#define E_EDGE 200000

// ---------------- scratch arena (floats) ----------------
#define SZ_S ((size_t)N_STMT * C_DIM)   // 12.8M
#define SZ_F ((size_t)N_FUNC * C_DIM)   // 6.4M
#define OFF_X0   ((size_t)0)
#define OFF_X1   (OFF_X0 + SZ_S)
#define OFF_XN0  (OFF_X1 + SZ_F)
#define OFF_XN1  (OFF_XN0 + SZ_S)
#define OFF_K0   (OFF_XN1 + SZ_F)
#define OFF_Q0   (OFF_K0 + SZ_S)
#define OFF_V0   (OFF_Q0 + SZ_S)
#define OFF_K1   (OFF_V0 + SZ_S)
#define OFF_Q1   (OFF_K1 + SZ_F)
#define OFF_V1   (OFF_Q1 + SZ_F)
#define OFF_KR   (OFF_V1 + SZ_F)
#define OFF_VR   (OFF_KR + SZ_S)
#define OFF_AGG0 (OFF_VR + SZ_S)
#define OFF_AGG1 (OFF_AGG0 + SZ_S)
#define OFF_LOG  (OFF_AGG1 + SZ_F)
#define OFF_M    (OFF_LOG + (size_t)E_EDGE * H_HEAD)
#define OFF_SS   (OFF_M + (size_t)N_STMT * H_HEAD)
#define SCRATCH_TOTAL (OFF_SS + (size_t)N_STMT * H_HEAD)

__device__ float g_scratch[SCRATCH_TOTAL];

// ---------------- device helpers ----------------
__device__ __forceinline__ float gelu_tanh(float x) {
    const float c = 0.7978845608028654f;  // sqrt(2/pi)
    float x3 = x * x * x;
    return 0.5f * x * (1.0f + tanhf(c * (x + 0.044715f * x3)));
}

__device__ __forceinline__ void atomicMaxF(float* addr, float v) {
    if (v >= 0.0f) atomicMax((int*)addr, __float_as_int(v));
    else           atomicMin((unsigned int*)addr, __float_as_uint(v));
}

// ---------------- fills ----------------
__global__ void fill_kernel(float* __restrict__ p, float v, int n) {
    int i = blockIdx.x * blockDim.x + threadIdx.x;
    if (i < n) p[i] = v;
}

// init m = -inf and s = 0 in one pass
__global__ void init_ms_kernel(float* __restrict__ m, float* __restrict__ s, int n) {
    int i = blockIdx.x * blockDim.x + threadIdx.x;
    if (i < n) { m[i] = -INFINITY; s[i] = 0.0f; }
}

// s <- 1/(s + 1e-16)
__global__ void inv_kernel(float* __restrict__ s, int n) {
    int i = blockIdx.x * blockDim.x + threadIdx.x;
    if (i < n) s[i] = 1.0f / (s[i] + 1e-16f);
}

// ---------------- embedding mean-pool + relu ----------------
__global__ void pool_kernel(const int* __restrict__ tok, const float* __restrict__ emb,
                            float* __restrict__ out, int N) {
    int n = blockIdx.x;
    int c = threadIdx.x;
    __shared__ int ts[T_TOK];
    if (c < T_TOK) ts[c] = tok[n * T_TOK + c];
    __syncthreads();
    float s = 0.0f;
#pragma unroll
    for (int t = 0; t < T_TOK; t++)
        s += emb[(size_t)ts[t] * C_DIM + c];
    s *= (1.0f / (float)T_TOK);
    out[(size_t)n * C_DIM + c] = fmaxf(s, 0.0f);
}

// ---------------- GEMM: Y[N,128] = epi( act_in(X)[N,128] @ W[128,128] + b ) ----------------
// 128-row block, 256 threads, 8x8 microtile per thread.
// EPI: 0 = none, 1 = relu, 2 = skip-blend (g*o + (1-g)*Xold, g = sigmoid(*skipp))
#define BM 128
#define BK 16
template<int IN_GELU, int EPI>
__global__ void __launch_bounds__(256, 2)
gemm128b(const float* __restrict__ X, const float* __restrict__ W,
         const float* __restrict__ bias, float* __restrict__ Y,
         const float* __restrict__ Xold, const float* __restrict__ skipp,
         int N) {
    __shared__ float Xs[BM][BK];      // 8 KB
    __shared__ float Ws[BK][C_DIM];   // 8 KB
    int tid = threadIdx.x;            // 256
    int tx = tid & 15;                // col group: cols tx*8 .. tx*8+7
    int ty = tid >> 4;                // row group: rows ty*8 .. ty*8+7
    int row0 = blockIdx.x * BM;

    float acc[8][8];
#pragma unroll
    for (int i = 0; i < 8; i++)
#pragma unroll
        for (int j = 0; j < 8; j++) acc[i][j] = 0.0f;

    for (int kc = 0; kc < C_DIM; kc += BK) {
        // X tile: 128x16 floats = 512 float4, 2 per thread (conflict-free stores)
#pragma unroll
        for (int v = 0; v < 2; v++) {
            int idx = tid + v * 256;
            int r = idx >> 2;              // 0..127
            int kk = (idx & 3) << 2;       // 0,4,8,12
            int grow = row0 + r;
            float4 val;
            if (grow < N) val = *(const float4*)&X[(size_t)grow * C_DIM + kc + kk];
            else          val = make_float4(0.f, 0.f, 0.f, 0.f);
            if (IN_GELU) {
                val.x = gelu_tanh(val.x); val.y = gelu_tanh(val.y);
                val.z = gelu_tanh(val.z); val.w = gelu_tanh(val.w);
            }
            *(float4*)&Xs[r][kk] = val;
        }
        // W tile: 16x128 floats = 512 float4, 2 per thread
#pragma unroll
        for (int v = 0; v < 2; v++) {
            int idx = tid + v * 256;
            int r = idx >> 5;              // 0..15
            int cc = (idx & 31) << 2;      // 0..124
            *(float4*)&Ws[r][cc] = *(const float4*)&W[(size_t)(kc + r) * C_DIM + cc];
        }
        __syncthreads();
#pragma unroll
        for (int k = 0; k < BK; k++) {
            float b[8];
            *(float4*)&b[0] = *(float4*)&Ws[k][tx * 8];
            *(float4*)&b[4] = *(float4*)&Ws[k][tx * 8 + 4];
#pragma unroll
            for (int i = 0; i < 8; i++) {
                float a = Xs[ty * 8 + i][k];
#pragma unroll
                for (int j = 0; j < 8; j++)
                    acc[i][j] = fmaf(a, b[j], acc[i][j]);
            }
        }
        __syncthreads();
    }

    // epilogue
    float bb[8];
    *(float4*)&bb[0] = *(const float4*)&bias[tx * 8];
    *(float4*)&bb[4] = *(const float4*)&bias[tx * 8 + 4];
    float g = 0.0f, og = 0.0f;
    if (EPI == 2) {
        g = 1.0f / (1.0f + expf(-skipp[0]));
        og = 1.0f - g;
    }
#pragma unroll
    for (int i = 0; i < 8; i++) {
        int grow = row0 + ty * 8 + i;
        if (grow < N) {
            float o[8];
#pragma unroll
            for (int j = 0; j < 8; j++) {
                float vv = acc[i][j] + bb[j];
                if (EPI == 1) vv = fmaxf(vv, 0.0f);
                o[j] = vv;
            }
            if (EPI == 2) {
                float4 x0 = *(const float4*)&Xold[(size_t)grow * C_DIM + tx * 8];
                float4 x1 = *(const float4*)&Xold[(size_t)grow * C_DIM + tx * 8 + 4];
                o[0] = g * o[0] + og * x0.x; o[1] = g * o[1] + og * x0.y;
                o[2] = g * o[2] + og * x0.z; o[3] = g * o[3] + og * x0.w;
                o[4] = g * o[4] + og * x1.x; o[5] = g * o[5] + og * x1.y;
                o[6] = g * o[6] + og * x1.z; o[7] = g * o[7] + og * x1.w;
            }
            *(float4*)&Y[(size_t)grow * C_DIM + tx * 8]     = *(float4*)&o[0];
            *(float4*)&Y[(size_t)grow * C_DIM + tx * 8 + 4] = *(float4*)&o[4];
        }
    }
}

// ---------------- fused per-head relation transforms ----------------
// kr[n,h,e] = sum_d K[n,h,d]*A[h,d,e];  vr[n,h,e] = sum_d V[n,h,d]*M[h,d,e]
__global__ void rel2_kernel(const float* __restrict__ K, const float* __restrict__ V,
                            const float* __restrict__ A, const float* __restrict__ M,
                            float* __restrict__ KR, float* __restrict__ VR, int N) {
    __shared__ float As[H_HEAD * D_HEAD * D_HEAD];  // 2048 floats
    __shared__ float Ms[H_HEAD * D_HEAD * D_HEAD];
    __shared__ float kin[4][C_DIM];
    __shared__ float vin[4][C_DIM];
    int tid = threadIdx.y * C_DIM + threadIdx.x;    // 512 threads
    for (int i = tid; i < H_HEAD * D_HEAD * D_HEAD; i += 512) {
        As[i] = A[i];
        Ms[i] = M[i];
    }
    int n = blockIdx.x * 4 + threadIdx.y;
    int c = threadIdx.x;
    int h = c >> 4, e = c & 15;
    if (n < N) {
        kin[threadIdx.y][c] = K[(size_t)n * C_DIM + c];
        vin[threadIdx.y][c] = V[(size_t)n * C_DIM + c];
    }
    __syncthreads();
    if (n < N) {
        float sk = 0.0f, sv = 0.0f;
#pragma unroll
        for (int d = 0; d < D_HEAD; d++) {
            float a = As[(h * 16 + d) * 16 + e];
            float m = Ms[(h * 16 + d) * 16 + e];
            sk = fmaf(kin[threadIdx.y][h * 16 + d], a, sk);
            sv = fmaf(vin[threadIdx.y][h * 16 + d], m, sv);
        }
        KR[(size_t)n * C_DIM + c] = sk;
        VR[(size_t)n * C_DIM + c] = sv;
    }
}

// ---------------- edge kernels ----------------
__global__ void edge_logits_kernel(const int* __restrict__ src, const int* __restrict__ dst,
                                   const float* __restrict__ Q, const float* __restrict__ KR,
                                   const float* __restrict__ prel,
                                   float* __restrict__ logits, float* __restrict__ m) {
    int idx = blockIdx.x * blockDim.x + threadIdx.x;
    if (idx >= E_EDGE * H_HEAD) return;
    int e = idx >> 3;
    int h = idx & 7;
    int s = src[e], d = dst[e];
    const float4* qp = (const float4*)&Q[(size_t)d * C_DIM + h * 16];
    const float4* kp = (const float4*)&KR[(size_t)s * C_DIM + h * 16];
    float acc = 0.0f;
#pragma unroll
    for (int i = 0; i < 4; i++) {
        float4 qa = qp[i], ka = kp[i];
        acc += qa.x * ka.x + qa.y * ka.y + qa.z * ka.z + qa.w * ka.w;
    }
    float lg = acc * prel[h] * 0.25f;   // scale = 1/sqrt(16)
    logits[idx] = lg;
    atomicMaxF(&m[d * H_HEAD + h], lg);
}

__global__ void edge_exp_kernel(const int* __restrict__ dst,
                                float* __restrict__ logits,
                                const float* __restrict__ m, float* __restrict__ ssum) {
    int idx = blockIdx.x * blockDim.x + threadIdx.x;
    if (idx >= E_EDGE * H_HEAD) return;
    int e = idx >> 3;
    int h = idx & 7;
    int d = dst[e];
    float v = expf(logits[idx] - m[d * H_HEAD + h]);
    logits[idx] = v;
    atomicAdd(&ssum[d * H_HEAD + h], v);
}

// sinv holds precomputed 1/(s+1e-16)
__global__ void edge_scatter_kernel(const int* __restrict__ src, const int* __restrict__ dst,
                                    const float* __restrict__ VR, const float* __restrict__ logits,
                                    const float* __restrict__ sinv, float* __restrict__ agg) {
    int idx = blockIdx.x * blockDim.x + threadIdx.x;
    if (idx >= E_EDGE * H_HEAD) return;
    int e = idx >> 3;
    int h = idx & 7;
    int sn = src[e], d = dst[e];
    float alpha = logits[idx] * sinv[d * H_HEAD + h];
    const float4* vp = (const float4*)&VR[(size_t)sn * C_DIM + h * 16];
    float* ap = &agg[(size_t)d * C_DIM + h * 16];
#pragma unroll
    for (int i = 0; i < 4; i++) {
        float4 vv = vp[i];
        atomicAdd(ap + 4 * i + 0, vv.x * alpha);
        atomicAdd(ap + 4 * i + 1, vv.y * alpha);
        atomicAdd(ap + 4 * i + 2, vv.z * alpha);
        atomicAdd(ap + 4 * i + 3, vv.w * alpha);
    }
}

// ---------------- host orchestration ----------------
static inline int cdiv(int a, int b) { return (a + b - 1) / b; }

extern "C" void kernel_launch(void* const* d_in, const int* in_sizes, int n_in,
                              void* d_out, int out_size) {
    (void)in_sizes; (void)n_in; (void)out_size;
    const int*   tok_s = (const int*)d_in[0];
    const int*   tok_f = (const int*)d_in[1];
    const int*   esrc[3] = {(const int*)d_in[2], (const int*)d_in[4], (const int*)d_in[6]};
    const int*   edst[3] = {(const int*)d_in[3], (const int*)d_in[5], (const int*)d_in[7]};
    const float* emb   = (const float*)d_in[8];
    const float* lin_w = (const float*)d_in[9];
    const float* lin_b = (const float*)d_in[10];
    const float* kw = (const float*)d_in[11], *kbi = (const float*)d_in[12];
    const float* qw = (const float*)d_in[13], *qbi = (const float*)d_in[14];
    const float* vw = (const float*)d_in[15], *vbi = (const float*)d_in[16];
    const float* aw = (const float*)d_in[17], *abi = (const float*)d_in[18];
    const float* skip  = (const float*)d_in[19];
    const float* a_rel = (const float*)d_in[20];
    const float* m_rel = (const float*)d_in[21];
    const float* p_rel = (const float*)d_in[22];
    float* out = (float*)d_out;

    float* S = nullptr;
    cudaGetSymbolAddress((void**)&S, g_scratch);

    float* x[2]    = {S + OFF_X0,  S + OFF_X1};
    float* xn[2]   = {S + OFF_XN0, S + OFF_XN1};
    float* bufK[2] = {S + OFF_K0,  S + OFF_K1};
    float* bufQ[2] = {S + OFF_Q0,  S + OFF_Q1};
    float* bufV[2] = {S + OFF_V0,  S + OFF_V1};
    float* kr   = S + OFF_KR;
    float* vr   = S + OFF_VR;
    float* agg[2] = {S + OFF_AGG0, S + OFF_AGG1};
    float* lg   = S + OFF_LOG;
    float* mbuf = S + OFF_M;
    float* sbuf = S + OFF_SS;

    const int NN[2] = {N_STMT, N_FUNC};
    const int ST[3] = {0, 0, 1};
    const int DT[3] = {0, 1, 0};
    const int nEH = E_EDGE * H_HEAD;

    // ---- encode: pool(+relu) into agg buffers, then per-type linear + relu ----
    pool_kernel<<<N_STMT, C_DIM>>>(tok_s, emb, agg[0], N_STMT);
    pool_kernel<<<N_FUNC, C_DIM>>>(tok_f, emb, agg[1], N_FUNC);
    gemm128b<0, 1><<<cdiv(N_STMT, BM), 256>>>(agg[0], lin_w, lin_b, x[0], nullptr, nullptr, N_STMT);
    gemm128b<0, 1><<<cdiv(N_FUNC, BM), 256>>>(agg[1], lin_w + C_DIM * C_DIM, lin_b + C_DIM,
                                              x[1], nullptr, nullptr, N_FUNC);

    float* cur[2] = {x[0], x[1]};
    float* nxt[2] = {xn[0], xn[1]};

    for (int l = 0; l < L_LAYER; l++) {
        // projections
        for (int t = 0; t < 2; t++) {
            size_t wo = (size_t)(l * 2 + t) * C_DIM * C_DIM;
            size_t bo = (size_t)(l * 2 + t) * C_DIM;
            int nb = cdiv(NN[t], BM);
            gemm128b<0, 0><<<nb, 256>>>(cur[t], kw + wo, kbi + bo, bufK[t], nullptr, nullptr, NN[t]);
            gemm128b<0, 0><<<nb, 256>>>(cur[t], qw + wo, qbi + bo, bufQ[t], nullptr, nullptr, NN[t]);
            gemm128b<0, 0><<<nb, 256>>>(cur[t], vw + wo, vbi + bo, bufV[t], nullptr, nullptr, NN[t]);
        }
        // zero both aggregators (contiguous in the arena) in one launch
        fill_kernel<<<cdiv((int)(SZ_S + SZ_F), 256), 256>>>(agg[0], 0.0f, (int)(SZ_S + SZ_F));

        for (int r = 0; r < 3; r++) {
            int st = ST[r], dt = DT[r];
            size_t ro = (size_t)(l * 3 + r) * H_HEAD * D_HEAD * D_HEAD;
            dim3 rb(C_DIM, 4);
            rel2_kernel<<<cdiv(NN[st], 4), rb>>>(bufK[st], bufV[st], a_rel + ro, m_rel + ro,
                                                 kr, vr, NN[st]);

            int ndh = NN[dt] * H_HEAD;
            init_ms_kernel<<<cdiv(ndh, 256), 256>>>(mbuf, sbuf, ndh);

            const float* pr = p_rel + (size_t)(l * 3 + r) * H_HEAD;
            edge_logits_kernel<<<cdiv(nEH, 256), 256>>>(esrc[r], edst[r], bufQ[dt], kr, pr, lg, mbuf);
            edge_exp_kernel<<<cdiv(nEH, 256), 256>>>(edst[r], lg, mbuf, sbuf);
            inv_kernel<<<cdiv(ndh, 256), 256>>>(sbuf, ndh);
            edge_scatter_kernel<<<cdiv(nEH, 256), 256>>>(esrc[r], edst[r], vr, lg, sbuf, agg[dt]);
        }

        // output projection with gelu-in + skip blend
        for (int t = 0; t < 2; t++) {
            size_t wo = (size_t)(l * 2 + t) * C_DIM * C_DIM;
            size_t bo = (size_t)(l * 2 + t) * C_DIM;
            float* yo = (l == L_LAYER - 1)
                        ? out + (t == 1 ? (size_t)N_STMT * C_DIM : 0)
                        : nxt[t];
            gemm128b<1, 2><<<cdiv(NN[t], BM), 256>>>(agg[t], aw + wo, abi + bo, yo,
                                                     cur[t], skip + (l * 2 + t), NN[t]);
        }
        // swap
        float* t0 = cur[0]; float* t1 = cur[1];
        cur[0] = nxt[0]; cur[1] = nxt[1];
        nxt[0] = t0; nxt[1] = t1;
    }
}

// round 9
// speedup vs baseline: 1.3844x; 1.1510x over previous
#include <cuda_runtime.h>
#include <math.h>

// ---------------- problem constants ----------------
#define N_STMT 100000
#define N_FUNC 50000
#define T_TOK  16
#define VOCAB  50000
#define C_DIM  128
#define H_HEAD 8
#define D_HEAD 16
#define L_LAYER 2
#define E_EDGE 200000

// ---------------- scratch arena ----------------
#define SZ_S ((size_t)N_STMT * C_DIM)   // 12.8M floats
#define SZ_F ((size_t)N_FUNC * C_DIM)   // 6.4M floats
#define OFF_X0   ((size_t)0)
#define OFF_X1   (OFF_X0 + SZ_S)
#define OFF_XN0  (OFF_X1 + SZ_F)
#define OFF_XN1  (OFF_XN0 + SZ_S)
#define OFF_K0   (OFF_XN1 + SZ_F)
#define OFF_Q0   (OFF_K0 + SZ_S)
#define OFF_V0   (OFF_Q0 + SZ_S)
#define OFF_K1   (OFF_V0 + SZ_S)
#define OFF_Q1   (OFF_K1 + SZ_F)
#define OFF_V1   (OFF_Q1 + SZ_F)
#define OFF_KR   (OFF_V1 + SZ_F)
#define OFF_VR   (OFF_KR + SZ_S)
#define OFF_AGG0 (OFF_VR + SZ_S)
#define OFF_AGG1 (OFF_AGG0 + SZ_S)
// CSR int region (viewed as int*): 3 relations of (rowptr, perm, cursor)
#define OFF_CSR  (OFF_AGG1 + SZ_F)
#define CSR_INTS ((size_t)1100016)
#define SCRATCH_TOTAL (OFF_CSR + CSR_INTS)

__device__ float g_scratch[SCRATCH_TOTAL];

// ---------------- device helpers ----------------
__device__ __forceinline__ float gelu_tanh(float x) {
    const float c = 0.7978845608028654f;  // sqrt(2/pi)
    float x3 = x * x * x;
    return 0.5f * x * (1.0f + tanhf(c * (x + 0.044715f * x3)));
}

// ---------------- fills / small utils ----------------
__global__ void fill_kernel(float* __restrict__ p, float v, int n) {
    int i = blockIdx.x * blockDim.x + threadIdx.x;
    if (i < n) p[i] = v;
}
__global__ void zero_int_kernel(int* __restrict__ p, int n) {
    int i = blockIdx.x * blockDim.x + threadIdx.x;
    if (i < n) p[i] = 0;
}
__global__ void copy_int_kernel(const int* __restrict__ a, int* __restrict__ b, int n) {
    int i = blockIdx.x * blockDim.x + threadIdx.x;
    if (i < n) b[i] = a[i];
}

// ---------------- CSR build ----------------
__global__ void count_kernel(const int* __restrict__ dst, int* __restrict__ deg, int n) {
    int i = blockIdx.x * blockDim.x + threadIdx.x;
    if (i < n) atomicAdd(&deg[dst[i]], 1);
}
// single-block exclusive scan: rowptr[0..N] from deg[0..N-1]
__global__ void scan_kernel(const int* __restrict__ deg, int* __restrict__ rowptr, int N) {
    __shared__ int part[1024];
    int tid = threadIdx.x;
    int chunk = (N + 1023) >> 10;
    int start = tid * chunk;
    int end = min(start + chunk, N);
    int s = 0;
    for (int i = start; i < end; i++) s += deg[i];
    part[tid] = s;
    __syncthreads();
    for (int d = 1; d < 1024; d <<= 1) {
        int v = (tid >= d) ? part[tid - d] : 0;
        __syncthreads();
        part[tid] += v;
        __syncthreads();
    }
    int off = part[tid] - s;  // exclusive prefix
    for (int i = start; i < end; i++) { rowptr[i] = off; off += deg[i]; }
    if (tid == 1023) rowptr[N] = part[1023];
}
__global__ void fill_csr_kernel(const int* __restrict__ dst, int* __restrict__ cursor,
                                int* __restrict__ perm, int n) {
    int i = blockIdx.x * blockDim.x + threadIdx.x;
    if (i < n) {
        int pos = atomicAdd(&cursor[dst[i]], 1);
        perm[pos] = i;
    }
}

// ---------------- embedding mean-pool + relu ----------------
__global__ void pool_kernel(const int* __restrict__ tok, const float* __restrict__ emb,
                            float* __restrict__ out, int N) {
    int n = blockIdx.x;
    int c = threadIdx.x;
    __shared__ int ts[T_TOK];
    if (c < T_TOK) ts[c] = tok[n * T_TOK + c];
    __syncthreads();
    float s = 0.0f;
#pragma unroll
    for (int t = 0; t < T_TOK; t++)
        s += emb[(size_t)ts[t] * C_DIM + c];
    s *= (1.0f / (float)T_TOK);
    out[(size_t)n * C_DIM + c] = fmaxf(s, 0.0f);
}

// ---------------- GEMM: Y[N,128] = epi( act_in(X)[N,128] @ W[128,128] + b ) ----------------
// 128-row block, 256 threads, 8x8 microtile, X stored k-major in smem (padded).
// EPI: 0 = none, 1 = relu, 2 = skip-blend
#define BM 128
#define BK 32
#define XPAD (BM + 4)
template<int IN_GELU, int EPI>
__global__ void __launch_bounds__(256, 2)
gemm128b(const float* __restrict__ X, const float* __restrict__ W,
         const float* __restrict__ bias, float* __restrict__ Y,
         const float* __restrict__ Xold, const float* __restrict__ skipp,
         int N) {
    __shared__ float Xs[BK][XPAD];    // k-major, ~16.9 KB
    __shared__ float Ws[BK][C_DIM];   // 16 KB
    int tid = threadIdx.x;            // 256
    int tx = tid & 15;                // col group: cols tx*8 .. tx*8+7
    int ty = tid >> 4;                // row group: rows ty*8 .. ty*8+7
    int row0 = blockIdx.x * BM;

    float acc[8][8];
#pragma unroll
    for (int i = 0; i < 8; i++)
#pragma unroll
        for (int j = 0; j < 8; j++) acc[i][j] = 0.0f;

    for (int kc = 0; kc < C_DIM; kc += BK) {
        // X tile: 128 rows x 32 k = 1024 float4, 4 per thread, transposed into Xs
#pragma unroll
        for (int v = 0; v < 4; v++) {
            int idx = tid + v * 256;
            int r = idx >> 3;              // 0..127
            int kk = (idx & 7) << 2;       // 0,4,...,28
            int grow = row0 + r;
            float4 val;
            if (grow < N) val = *(const float4*)&X[(size_t)grow * C_DIM + kc + kk];
            else          val = make_float4(0.f, 0.f, 0.f, 0.f);
            if (IN_GELU) {
                val.x = gelu_tanh(val.x); val.y = gelu_tanh(val.y);
                val.z = gelu_tanh(val.z); val.w = gelu_tanh(val.w);
            }
            Xs[kk + 0][r] = val.x;
            Xs[kk + 1][r] = val.y;
            Xs[kk + 2][r] = val.z;
            Xs[kk + 3][r] = val.w;
        }
        // W tile: 32 x 128 = 1024 float4, 4 per thread
#pragma unroll
        for (int v = 0; v < 4; v++) {
            int idx = tid + v * 256;
            int r = idx >> 5;              // 0..31
            int cc = (idx & 31) << 2;      // 0..124
            *(float4*)&Ws[r][cc] = *(const float4*)&W[(size_t)(kc + r) * C_DIM + cc];
        }
        __syncthreads();
#pragma unroll
        for (int k = 0; k < BK; k++) {
            float a[8], b[8];
            *(float4*)&a[0] = *(float4*)&Xs[k][ty * 8];
            *(float4*)&a[4] = *(float4*)&Xs[k][ty * 8 + 4];
            *(float4*)&b[0] = *(float4*)&Ws[k][tx * 8];
            *(float4*)&b[4] = *(float4*)&Ws[k][tx * 8 + 4];
#pragma unroll
            for (int i = 0; i < 8; i++)
#pragma unroll
                for (int j = 0; j < 8; j++)
                    acc[i][j] = fmaf(a[i], b[j], acc[i][j]);
        }
        __syncthreads();
    }

    // epilogue
    float bb[8];
    *(float4*)&bb[0] = *(const float4*)&bias[tx * 8];
    *(float4*)&bb[4] = *(const float4*)&bias[tx * 8 + 4];
    float g = 0.0f, og = 0.0f;
    if (EPI == 2) {
        g = 1.0f / (1.0f + expf(-skipp[0]));
        og = 1.0f - g;
    }
#pragma unroll
    for (int i = 0; i < 8; i++) {
        int grow = row0 + ty * 8 + i;
        if (grow < N) {
            float o[8];
#pragma unroll
            for (int j = 0; j < 8; j++) {
                float vv = acc[i][j] + bb[j];
                if (EPI == 1) vv = fmaxf(vv, 0.0f);
                o[j] = vv;
            }
            if (EPI == 2) {
                float4 x0 = *(const float4*)&Xold[(size_t)grow * C_DIM + tx * 8];
                float4 x1 = *(const float4*)&Xold[(size_t)grow * C_DIM + tx * 8 + 4];
                o[0] = g * o[0] + og * x0.x; o[1] = g * o[1] + og * x0.y;
                o[2] = g * o[2] + og * x0.z; o[3] = g * o[3] + og * x0.w;
                o[4] = g * o[4] + og * x1.x; o[5] = g * o[5] + og * x1.y;
                o[6] = g * o[6] + og * x1.z; o[7] = g * o[7] + og * x1.w;
            }
            *(float4*)&Y[(size_t)grow * C_DIM + tx * 8]     = *(float4*)&o[0];
            *(float4*)&Y[(size_t)grow * C_DIM + tx * 8 + 4] = *(float4*)&o[4];
        }
    }
}

// ---------------- fused per-head relation transforms ----------------
__global__ void rel2_kernel(const float* __restrict__ K, const float* __restrict__ V,
                            const float* __restrict__ A, const float* __restrict__ M,
                            float* __restrict__ KR, float* __restrict__ VR, int N) {
    __shared__ float As[H_HEAD * D_HEAD * D_HEAD];  // 2048 floats
    __shared__ float Ms[H_HEAD * D_HEAD * D_HEAD];
    __shared__ float kin[4][C_DIM];
    __shared__ float vin[4][C_DIM];
    int tid = threadIdx.y * C_DIM + threadIdx.x;    // 512 threads
    for (int i = tid; i < H_HEAD * D_HEAD * D_HEAD; i += 512) {
        As[i] = A[i];
        Ms[i] = M[i];
    }
    int n = blockIdx.x * 4 + threadIdx.y;
    int c = threadIdx.x;
    int h = c >> 4, e = c & 15;
    if (n < N) {
        kin[threadIdx.y][c] = K[(size_t)n * C_DIM + c];
        vin[threadIdx.y][c] = V[(size_t)n * C_DIM + c];
    }
    __syncthreads();
    if (n < N) {
        float sk = 0.0f, sv = 0.0f;
#pragma unroll
        for (int d = 0; d < D_HEAD; d++) {
            float a = As[(h * 16 + d) * 16 + e];
            float m = Ms[(h * 16 + d) * 16 + e];
            sk = fmaf(kin[threadIdx.y][h * 16 + d], a, sk);
            sv = fmaf(vin[threadIdx.y][h * 16 + d], m, sv);
        }
        KR[(size_t)n * C_DIM + c] = sk;
        VR[(size_t)n * C_DIM + c] = sv;
    }
}

// ---------------- CSR gather: one-pass online softmax + aggregation ----------------
// thread = (dst, head); agg += softmax-weighted sum of VR over incoming edges.
__global__ void gather_kernel(const int* __restrict__ rowptr, const int* __restrict__ perm,
                              const int* __restrict__ srcarr,
                              const float* __restrict__ Q, const float* __restrict__ KR,
                              const float* __restrict__ VR, const float* __restrict__ prel,
                              float* __restrict__ agg, int Ndst) {
    int idx = blockIdx.x * blockDim.x + threadIdx.x;
    if (idx >= Ndst * H_HEAD) return;
    int d = idx >> 3, h = idx & 7;
    int beg = rowptr[d], end = rowptr[d + 1];
    if (beg == end) return;   // no incoming edges: contribution is zero
    float pscale = prel[h] * 0.25f;   // 1/sqrt(16)
    const float4* qp = (const float4*)&Q[(size_t)d * C_DIM + h * 16];
    float4 q0 = qp[0], q1 = qp[1], q2 = qp[2], q3 = qp[3];
    float m = -INFINITY, s = 0.0f;
    float acc[16];
#pragma unroll
    for (int i = 0; i < 16; i++) acc[i] = 0.0f;
    for (int j = beg; j < end; j++) {
        int sn = srcarr[perm[j]];
        const float4* kp = (const float4*)&KR[(size_t)sn * C_DIM + h * 16];
        float4 k0 = kp[0], k1 = kp[1], k2 = kp[2], k3 = kp[3];
        float l = q0.x * k0.x + q0.y * k0.y + q0.z * k0.z + q0.w * k0.w
                + q1.x * k1.x + q1.y * k1.y + q1.z * k1.z + q1.w * k1.w
                + q2.x * k2.x + q2.y * k2.y + q2.z * k2.z + q2.w * k2.w
                + q3.x * k3.x + q3.y * k3.y + q3.z * k3.z + q3.w * k3.w;
        l *= pscale;
        float mn = fmaxf(m, l);
        float sc = expf(m - mn);   // 0 on first edge (m = -inf)
        float w  = expf(l - mn);
        s = s * sc + w;
        m = mn;
        const float4* vp = (const float4*)&VR[(size_t)sn * C_DIM + h * 16];
#pragma unroll
        for (int i = 0; i < 4; i++) {
            float4 v = vp[i];
            acc[4 * i + 0] = acc[4 * i + 0] * sc + w * v.x;
            acc[4 * i + 1] = acc[4 * i + 1] * sc + w * v.y;
            acc[4 * i + 2] = acc[4 * i + 2] * sc + w * v.z;
            acc[4 * i + 3] = acc[4 * i + 3] * sc + w * v.w;
        }
    }
    float inv = 1.0f / (s + 1e-16f);
    float4* ap = (float4*)&agg[(size_t)d * C_DIM + h * 16];
#pragma unroll
    for (int i = 0; i < 4; i++) {
        float4 a = ap[i];
        a.x += acc[4 * i + 0] * inv;
        a.y += acc[4 * i + 1] * inv;
        a.z += acc[4 * i + 2] * inv;
        a.w += acc[4 * i + 3] * inv;
        ap[i] = a;
    }
}

// ---------------- host orchestration ----------------
static inline int cdiv(int a, int b) { return (a + b - 1) / b; }

extern "C" void kernel_launch(void* const* d_in, const int* in_sizes, int n_in,
                              void* d_out, int out_size) {
    (void)in_sizes; (void)n_in; (void)out_size;
    const int*   tok_s = (const int*)d_in[0];
    const int*   tok_f = (const int*)d_in[1];
    const int*   esrc[3] = {(const int*)d_in[2], (const int*)d_in[4], (const int*)d_in[6]};
    const int*   edst[3] = {(const int*)d_in[3], (const int*)d_in[5], (const int*)d_in[7]};
    const float* emb   = (const float*)d_in[8];
    const float* lin_w = (const float*)d_in[9];
    const float* lin_b = (const float*)d_in[10];
    const float* kw = (const float*)d_in[11], *kbi = (const float*)d_in[12];
    const float* qw = (const float*)d_in[13], *qbi = (const float*)d_in[14];
    const float* vw = (const float*)d_in[15], *vbi = (const float*)d_in[16];
    const float* aw = (const float*)d_in[17], *abi = (const float*)d_in[18];
    const float* skip  = (const float*)d_in[19];
    const float* a_rel = (const float*)d_in[20];
    const float* m_rel = (const float*)d_in[21];
    const float* p_rel = (const float*)d_in[22];
    float* out = (float*)d_out;

    float* S = nullptr;
    cudaGetSymbolAddress((void**)&S, g_scratch);

    float* x[2]    = {S + OFF_X0,  S + OFF_X1};
    float* xn[2]   = {S + OFF_XN0, S + OFF_XN1};
    float* bufK[2] = {S + OFF_K0,  S + OFF_K1};
    float* bufQ[2] = {S + OFF_Q0,  S + OFF_Q1};
    float* bufV[2] = {S + OFF_V0,  S + OFF_V1};
    float* kr   = S + OFF_KR;
    float* vr   = S + OFF_VR;
    float* agg[2] = {S + OFF_AGG0, S + OFF_AGG1};

    const int NN[2] = {N_STMT, N_FUNC};
    const int ST[3] = {0, 0, 1};
    const int DT[3] = {0, 1, 0};

    // ---- CSR layout inside the int region ----
    int* csr = (int*)(S + OFF_CSR);
    const int ndst_r[3] = {N_STMT, N_FUNC, N_STMT};
    int* rp[3]; int* pm[3]; int* cu[3];
    {
        size_t off = 0;
        for (int r = 0; r < 3; r++) {
            rp[r] = csr + off; off += (size_t)ndst_r[r] + 1;
            pm[r] = csr + off; off += E_EDGE;
            cu[r] = csr + off; off += ndst_r[r];
        }
    }
    // build CSR for each relation (graph is layer-invariant)
    for (int r = 0; r < 3; r++) {
        int nd = ndst_r[r];
        zero_int_kernel<<<cdiv(nd, 256), 256>>>(cu[r], nd);
        count_kernel<<<cdiv(E_EDGE, 256), 256>>>(edst[r], cu[r], E_EDGE);
        scan_kernel<<<1, 1024>>>(cu[r], rp[r], nd);
        copy_int_kernel<<<cdiv(nd, 256), 256>>>(rp[r], cu[r], nd);
        fill_csr_kernel<<<cdiv(E_EDGE, 256), 256>>>(edst[r], cu[r], pm[r], E_EDGE);
    }

    // ---- encode: pool(+relu) into agg buffers, then per-type linear + relu ----
    pool_kernel<<<N_STMT, C_DIM>>>(tok_s, emb, agg[0], N_STMT);
    pool_kernel<<<N_FUNC, C_DIM>>>(tok_f, emb, agg[1], N_FUNC);
    gemm128b<0, 1><<<cdiv(N_STMT, BM), 256>>>(agg[0], lin_w, lin_b, x[0], nullptr, nullptr, N_STMT);
    gemm128b<0, 1><<<cdiv(N_FUNC, BM), 256>>>(agg[1], lin_w + C_DIM * C_DIM, lin_b + C_DIM,
                                              x[1], nullptr, nullptr, N_FUNC);

    float* cur[2] = {x[0], x[1]};
    float* nxt[2] = {xn[0], xn[1]};

    for (int l = 0; l < L_LAYER; l++) {
        // projections
        for (int t = 0; t < 2; t++) {
            size_t wo = (size_t)(l * 2 + t) * C_DIM * C_DIM;
            size_t bo = (size_t)(l * 2 + t) * C_DIM;
            int nb = cdiv(NN[t], BM);
            gemm128b<0, 0><<<nb, 256>>>(cur[t], kw + wo, kbi + bo, bufK[t], nullptr, nullptr, NN[t]);
            gemm128b<0, 0><<<nb, 256>>>(cur[t], qw + wo, qbi + bo, bufQ[t], nullptr, nullptr, NN[t]);
            gemm128b<0, 0><<<nb, 256>>>(cur[t], vw + wo, vbi + bo, bufV[t], nullptr, nullptr, NN[t]);
        }
        // zero both aggregators (contiguous in the arena) in one launch
        fill_kernel<<<cdiv((int)(SZ_S + SZ_F), 256), 256>>>(agg[0], 0.0f, (int)(SZ_S + SZ_F));

        for (int r = 0; r < 3; r++) {
            int st = ST[r], dt = DT[r];
            size_t ro = (size_t)(l * 3 + r) * H_HEAD * D_HEAD * D_HEAD;
            dim3 rb(C_DIM, 4);
            rel2_kernel<<<cdiv(NN[st], 4), rb>>>(bufK[st], bufV[st], a_rel + ro, m_rel + ro,
                                                 kr, vr, NN[st]);
            const float* pr = p_rel + (size_t)(l * 3 + r) * H_HEAD;
            gather_kernel<<<cdiv(NN[dt] * H_HEAD, 256), 256>>>(
                rp[r], pm[r], esrc[r], bufQ[dt], kr, vr, pr, agg[dt], NN[dt]);
        }

        // output projection with gelu-in + skip blend
        for (int t = 0; t < 2; t++) {
            size_t wo = (size_t)(l * 2 + t) * C_DIM * C_DIM;
            size_t bo = (size_t)(l * 2 + t) * C_DIM;
            float* yo = (l == L_LAYER - 1)
                        ? out + (t == 1 ? (size_t)N_STMT * C_DIM : 0)
                        : nxt[t];
            gemm128b<1, 2><<<cdiv(NN[t], BM), 256>>>(agg[t], aw + wo, abi + bo, yo,
                                                     cur[t], skip + (l * 2 + t), NN[t]);
        }
        // swap
        float* t0 = cur[0]; float* t1 = cur[1];
        cur[0] = nxt[0]; cur[1] = nxt[1];
        nxt[0] = t0; nxt[1] = t1;
    }
}